// round 1
// baseline (speedup 1.0000x reference)
#include <cuda_runtime.h>
#include <math.h>
#include <stdint.h>

typedef unsigned long long u64;

#define GMAX 10240
#define CH 384
#define NWARP 16
#define BLOCK (NWARP * 32)
#define ROWS_PER_BLOCK 64

// Precomputed SH table, duplicated-pair SoA:
// plane0 = {dup(Y0), dup(Y1)}, plane1 = {dup(Y2), dup(Y3)}, plane2 = {dup(Y4), dup(Y5)},
// plane3 = {dup(Y6), dup(Y7)}, plane4 = {dup(Y8), dup(gx)}, plane5 = {dup(gy), dup(gz)}
__device__ ulonglong2 g_dupP[6][GMAX];

__device__ __forceinline__ u64 dup2(float f) {
    u64 r; asm("mov.b64 %0, {%1, %1};" : "=l"(r) : "f"(f)); return r;
}
__device__ __forceinline__ u64 pk2(float lo, float hi) {
    u64 r; asm("mov.b64 %0, {%1, %2};" : "=l"(r) : "f"(lo), "f"(hi)); return r;
}
__device__ __forceinline__ void upk2(u64 v, float& lo, float& hi) {
    asm("mov.b64 {%0, %1}, %2;" : "=f"(lo), "=f"(hi) : "l"(v));
}
__device__ __forceinline__ u64 fma2(u64 a, u64 b, u64 c) {
    u64 r; asm("fma.rn.f32x2 %0, %1, %2, %3;" : "=l"(r) : "l"(a), "l"(b), "l"(c)); return r;
}
__device__ __forceinline__ u64 mul2(u64 a, u64 b) {
    u64 r; asm("mul.rn.f32x2 %0, %1, %2;" : "=l"(r) : "l"(a), "l"(b)); return r;
}

// ---------------------------------------------------------------------------
// Kernel 1: compute l=4 real SH basis (9 comps) per grid dir, store dup-packed.
// ---------------------------------------------------------------------------
__global__ void sh_precompute_kernel(const float* __restrict__ grid, int G) {
    int g = blockIdx.x * blockDim.x + threadIdx.x;
    if (g >= G) return;
    float gx = grid[3 * g + 0], gy = grid[3 * g + 1], gz = grid[3 * g + 2];
    float n = sqrtf(gx * gx + gy * gy + gz * gz);
    float inv = 1.0f / fmaxf(n, 1e-12f);
    float x = gx * inv, y = gy * inv, z = gz * inv;
    float x2 = x * x, y2 = y * y, z2 = z * z;
    float Y0 = 2.5033429417967046f * (x * y * (x2 - y2));
    float Y1 = 1.7701307697799304f * (y * z * (3.0f * x2 - y2));
    float Y2 = 0.9461746957575601f * (x * y * (7.0f * z2 - 1.0f));
    float Y3 = 0.6690465435572892f * (y * z * (7.0f * z2 - 3.0f));
    float Y4c = 0.10578554691520431f * (35.0f * z2 * z2 - 30.0f * z2 + 3.0f);
    float Y5 = 0.6690465435572892f * (x * z * (7.0f * z2 - 3.0f));
    float Y6 = 0.47308734787878004f * ((x2 - y2) * (7.0f * z2 - 1.0f));
    float Y7 = 1.7701307697799304f * (x * z * (x2 - y2));
    float Y8 = 0.6258357354491761f * (x2 * x2 - 6.0f * x2 * y2 + y2 * y2);
    g_dupP[0][g] = make_ulonglong2(dup2(Y0), dup2(Y1));
    g_dupP[1][g] = make_ulonglong2(dup2(Y2), dup2(Y3));
    g_dupP[2][g] = make_ulonglong2(dup2(Y4c), dup2(Y5));
    g_dupP[3][g] = make_ulonglong2(dup2(Y6), dup2(Y7));
    g_dupP[4][g] = make_ulonglong2(dup2(Y8), dup2(gx));
    g_dupP[5][g] = make_ulonglong2(dup2(gy), dup2(gz));
}

// ---------------------------------------------------------------------------
// Kernel 2: fused two-pass argmax + quaternion epilogue.
// Block = 512 threads = 16 warps, handles 64 rows (2 rows per lane, f32x2).
// Warps split the g-range of each smem chunk; all lanes of a warp broadcast-
// read the same g entry (conflict-free).
// ---------------------------------------------------------------------------
__global__ __launch_bounds__(BLOCK) void decoder_kernel(
    const float* __restrict__ f0,
    const float* __restrict__ f4,
    const float* __restrict__ grid,
    float* __restrict__ out,
    int B, int G)
{
    __shared__ ulonglong2 sPl[6][CH];
    __shared__ float s_pv[NWARP][ROWS_PER_BLOCK];
    __shared__ int s_pidx[NWARP][ROWS_PER_BLOCK];
    __shared__ float s_z[ROWS_PER_BLOCK][3];

    const int tid = threadIdx.x;
    const int lane = tid & 31;
    const int wid = tid >> 5;
    const int rowbase = blockIdx.x * ROWS_PER_BLOCK;
    const int r0 = rowbase + 2 * lane;
    const int r1 = r0 + 1;
    const float NEG_INF = __int_as_float(0xff800000);

    u64 F[9];
#pragma unroll
    for (int i = 0; i < 9; i++) {
        float a = (r0 < B) ? f4[r0 * 9 + i] : 0.0f;
        float b = (r1 < B) ? f4[r1 * 9 + i] : 0.0f;
        F[i] = pk2(a, b);
    }

    float bv0 = NEG_INF, bv1 = NEG_INF;
    int bi0 = 0, bi1 = 0;

    // ------------------- pass 1: argmax of signal -> z axis -----------------
    for (int base = 0; base < G; base += CH) {
        int cnt = min(CH, G - base);
        __syncthreads();
#pragma unroll
        for (int c = 0; c < 5; c++)
            for (int j = tid; j < cnt; j += BLOCK) sPl[c][j] = g_dupP[c][base + j];
        __syncthreads();
        for (int k = wid; k < cnt; k += NWARP) {
            ulonglong2 v0 = sPl[0][k], v1 = sPl[1][k], v2 = sPl[2][k],
                       v3 = sPl[3][k], v4 = sPl[4][k];
            u64 acc = mul2(F[0], v0.x);
            acc = fma2(F[1], v0.y, acc);
            acc = fma2(F[2], v1.x, acc);
            acc = fma2(F[3], v1.y, acc);
            acc = fma2(F[4], v2.x, acc);
            acc = fma2(F[5], v2.y, acc);
            acc = fma2(F[6], v3.x, acc);
            acc = fma2(F[7], v3.y, acc);
            acc = fma2(F[8], v4.x, acc);
            float slo, shi; upk2(acc, slo, shi);
            int g = base + k;
            if (slo > bv0) { bv0 = slo; bi0 = g; }
            if (shi > bv1) { bv1 = shi; bi1 = g; }
        }
    }
    s_pv[wid][2 * lane] = bv0;     s_pidx[wid][2 * lane] = bi0;
    s_pv[wid][2 * lane + 1] = bv1; s_pidx[wid][2 * lane + 1] = bi1;
    __syncthreads();
    if (tid < ROWS_PER_BLOCK) {
        float v = s_pv[0][tid]; int idx = s_pidx[0][tid];
#pragma unroll
        for (int w = 1; w < NWARP; w++) {
            float ov = s_pv[w][tid]; int oi = s_pidx[w][tid];
            if (ov > v || (ov == v && oi < idx)) { v = ov; idx = oi; }
        }
        s_z[tid][0] = grid[3 * idx + 0];
        s_z[tid][1] = grid[3 * idx + 1];
        s_z[tid][2] = grid[3 * idx + 2];
    }
    __syncthreads();

    u64 ZX = pk2(s_z[2 * lane][0], s_z[2 * lane + 1][0]);
    u64 ZY = pk2(s_z[2 * lane][1], s_z[2 * lane + 1][1]);
    u64 ZZ = pk2(s_z[2 * lane][2], s_z[2 * lane + 1][2]);

    bv0 = NEG_INF; bv1 = NEG_INF; bi0 = 0; bi1 = 0;

    // ------------- pass 2: masked argmax (|dot(z,g)| < 0.2) -> x axis -------
    for (int base = 0; base < G; base += CH) {
        int cnt = min(CH, G - base);
        __syncthreads();
#pragma unroll
        for (int c = 0; c < 6; c++)
            for (int j = tid; j < cnt; j += BLOCK) sPl[c][j] = g_dupP[c][base + j];
        __syncthreads();
        for (int k = wid; k < cnt; k += NWARP) {
            ulonglong2 v0 = sPl[0][k], v1 = sPl[1][k], v2 = sPl[2][k],
                       v3 = sPl[3][k], v4 = sPl[4][k], v5 = sPl[5][k];
            u64 acc = mul2(F[0], v0.x);
            acc = fma2(F[1], v0.y, acc);
            acc = fma2(F[2], v1.x, acc);
            acc = fma2(F[3], v1.y, acc);
            acc = fma2(F[4], v2.x, acc);
            acc = fma2(F[5], v2.y, acc);
            acc = fma2(F[6], v3.x, acc);
            acc = fma2(F[7], v3.y, acc);
            acc = fma2(F[8], v4.x, acc);
            u64 d = mul2(ZX, v4.y);
            d = fma2(ZY, v5.x, d);
            d = fma2(ZZ, v5.y, d);
            float slo, shi, dlo, dhi;
            upk2(acc, slo, shi); upk2(d, dlo, dhi);
            int g = base + k;
            if (fabsf(dlo) < 0.2f && slo > bv0) { bv0 = slo; bi0 = g; }
            if (fabsf(dhi) < 0.2f && shi > bv1) { bv1 = shi; bi1 = g; }
        }
    }
    s_pv[wid][2 * lane] = bv0;     s_pidx[wid][2 * lane] = bi0;
    s_pv[wid][2 * lane + 1] = bv1; s_pidx[wid][2 * lane + 1] = bi1;
    __syncthreads();

    // ------------------------ per-row epilogue ------------------------------
    if (tid < ROWS_PER_BLOCK) {
        int row = rowbase + tid;
        if (row < B) {
            float v = s_pv[0][tid]; int idx = s_pidx[0][tid];
#pragma unroll
            for (int w = 1; w < NWARP; w++) {
                float ov = s_pv[w][tid]; int oi = s_pidx[w][tid];
                if (ov > v || (ov == v && oi < idx)) { v = ov; idx = oi; }
            }
            float xr0 = grid[3 * idx + 0], xr1 = grid[3 * idx + 1], xr2 = grid[3 * idx + 2];
            float zr0 = s_z[tid][0], zr1 = s_z[tid][1], zr2 = s_z[tid][2];
            // z = normalize(z_raw)
            float zn = sqrtf(zr0 * zr0 + zr1 * zr1 + zr2 * zr2);
            float zinv = 1.0f / fmaxf(zn, 1e-12f);
            float z0 = zr0 * zinv, z1 = zr1 * zinv, z2 = zr2 * zinv;
            // x = normalize(x_raw - (x_raw . z) z)
            float pr = xr0 * z0 + xr1 * z1 + xr2 * z2;
            float x0 = xr0 - pr * z0, x1 = xr1 - pr * z1, x2 = xr2 - pr * z2;
            float xn = sqrtf(x0 * x0 + x1 * x1 + x2 * x2);
            float xinv = 1.0f / fmaxf(xn, 1e-12f);
            x0 *= xinv; x1 *= xinv; x2 *= xinv;
            // y = z cross x
            float y0 = z1 * x2 - z2 * x1;
            float y1 = z2 * x0 - z0 * x2;
            float y2 = z0 * x1 - z1 * x0;
            // R columns = [x y z]
            float m00 = x0, m01 = y0, m02 = z0;
            float m10 = x1, m11 = y1, m12 = z1;
            float m20 = x2, m21 = y2, m22 = z2;
            float qa0 = sqrtf(fmaxf(1.0f + m00 + m11 + m22, 0.0f));
            float qa1 = sqrtf(fmaxf(1.0f + m00 - m11 - m22, 0.0f));
            float qa2 = sqrtf(fmaxf(1.0f - m00 + m11 - m22, 0.0f));
            float qa3 = sqrtf(fmaxf(1.0f - m00 - m11 + m22, 0.0f));
            float c0[4] = {qa0 * qa0, m21 - m12, m02 - m20, m10 - m01};
            float c1[4] = {m21 - m12, qa1 * qa1, m10 + m01, m02 + m20};
            float c2[4] = {m02 - m20, m10 + m01, qa2 * qa2, m12 + m21};
            float c3[4] = {m10 - m01, m20 + m02, m21 + m12, qa3 * qa3};
            int best = 0; float bq = qa0;
            if (qa1 > bq) { bq = qa1; best = 1; }
            if (qa2 > bq) { bq = qa2; best = 2; }
            if (qa3 > bq) { bq = qa3; best = 3; }
            const float* cr = (best == 0) ? c0 : (best == 1) ? c1 : (best == 2) ? c2 : c3;
            float dn = 2.0f * fmaxf(bq, 0.1f);
            out[row * 4 + 0] = cr[0] / dn;
            out[row * 4 + 1] = cr[1] / dn;
            out[row * 4 + 2] = cr[2] / dn;
            out[row * 4 + 3] = cr[3] / dn;
            // boundary_map = f0 * 180/pi, stored after the q block
            out[4 * B + row] = f0[row] * 57.29577951308232f;
        }
    }
}

extern "C" void kernel_launch(void* const* d_in, const int* in_sizes, int n_in,
                              void* d_out, int out_size) {
    const float* f0 = (const float*)d_in[0];
    const float* f4 = (const float*)d_in[2];
    const float* grid = (const float*)d_in[4];
    int B = in_sizes[0];          // f0: [B,1]
    int G = in_sizes[4] / 3;      // grid_vecs: [G,3]
    if (G > GMAX) G = GMAX;

    sh_precompute_kernel<<<(G + 255) / 256, 256>>>(grid, G);

    int blocks = (B + ROWS_PER_BLOCK - 1) / ROWS_PER_BLOCK;
    decoder_kernel<<<blocks, BLOCK>>>(f0, f4, grid, (float*)d_out, B, G);
}